// round 1
// baseline (speedup 1.0000x reference)
#include <cuda_runtime.h>
#include <cstdint>

// Problem constants
#define NROWS 8192      // 8 * 1024
#define DIM   512
#define KCODES 16384
#define NSPLIT 8
#define TM 128
#define TN 128
#define KC 16
#define CHUNK (KCODES / NSPLIT)          // 2048 codes per split
#define TILES_PER_CHUNK (CHUNK / TN)     // 16

// Scratch (device globals: allocation-free per harness rules)
__device__ float  g_c2[KCODES];
__device__ float  g_x2[NROWS];
__device__ float  g_pval[NSPLIT * NROWS];
__device__ int    g_pidx[NSPLIT * NROWS];
__device__ int    g_idx[NROWS];
__device__ double g_loss;

// ---------------------------------------------------------------------------
// c2[j] = sum_k cb[j][k]^2  (rounding order irrelevant: c2 ~ 6e-7 << ulp grid)
// One warp per code row, float4 loads, warp reduce.
__global__ void c2_kernel(const float* __restrict__ cb) {
    int row  = blockIdx.x * 8 + (threadIdx.x >> 5);
    int lane = threadIdx.x & 31;
    const float4* p = reinterpret_cast<const float4*>(cb + (size_t)row * DIM);
    float s = 0.f;
#pragma unroll
    for (int q = 0; q < 4; q++) {
        float4 v = p[lane + 32 * q];
        s += v.x * v.x + v.y * v.y + v.z * v.z + v.w * v.w;
    }
#pragma unroll
    for (int o = 16; o; o >>= 1) s += __shfl_xor_sync(0xFFFFFFFFu, s, o);
    if (lane == 0) g_c2[row] = s;
}

// ---------------------------------------------------------------------------
// x2[r] = sum_k x[r][k]^2 with STRICT SEQUENTIAL fp32 rounding
// (emulates XLA-CPU naive reduce; intrinsics block FMA contraction).
// Thread 0 also zeroes the loss accumulator (runs before gather each replay).
__global__ void x2_kernel(const float* __restrict__ x) {
    int row = blockIdx.x * blockDim.x + threadIdx.x;
    if (row == 0) g_loss = 0.0;
    if (row >= NROWS) return;
    const float* p = x + (size_t)row * DIM;
    float acc = 0.f;
    for (int i = 0; i < DIM; i++) {
        float v = __ldg(p + i);
        acc = __fadd_rn(acc, __fmul_rn(v, v));
    }
    g_x2[row] = acc;
}

// ---------------------------------------------------------------------------
// Fused distance + argmin over one N-chunk.
// d = fl( fl( x2 - fl(2*dot) ) + c2 )  — exact replication of reference expr.
// Tie-break: first (lowest) index — ascending scan + strict '<' within thread,
// explicit (v,idx) compare across threads/chunks.
__global__ __launch_bounds__(256)
void argmin_kernel(const float* __restrict__ X, const float* __restrict__ CB) {
    __shared__ float As[KC][TM];
    __shared__ float Bs[KC][TN];
    __shared__ float c2s[TN];
    __shared__ float redv[TM][17];
    __shared__ int   redi[TM][17];

    const int t  = threadIdx.x;
    const int tx = t & 15;
    const int ty = t >> 4;
    const int row0     = blockIdx.x * TM;        // 0..63 tiles of rows
    const int chunk    = blockIdx.y;             // 0..NSPLIT-1
    const int col_base = chunk * CHUNK;

    float x2r[8];
#pragma unroll
    for (int i = 0; i < 8; i++) x2r[i] = g_x2[row0 + ty * 8 + i];

    float bestv[8];
    int   besti[8];
#pragma unroll
    for (int i = 0; i < 8; i++) { bestv[i] = 3.4e38f; besti[i] = 0x7fffffff; }

    for (int nt = 0; nt < TILES_PER_CHUNK; nt++) {
        const int col0 = col_base + nt * TN;
        __syncthreads();                       // protect c2s vs prev epilogue
        if (t < TN) c2s[t] = g_c2[col0 + t];

        float acc[8][8];
#pragma unroll
        for (int i = 0; i < 8; i++)
#pragma unroll
            for (int j = 0; j < 8; j++) acc[i][j] = 0.f;

        for (int k0 = 0; k0 < DIM; k0 += KC) {
            __syncthreads();
            // A tile: 128 rows x 16 k = 512 float4; 2 per thread
#pragma unroll
            for (int r2 = 0; r2 < 2; r2++) {
                int f = t + r2 * 256;
                int row = f >> 2;
                int q   = f & 3;
                float4 v = *reinterpret_cast<const float4*>(
                    X + (size_t)(row0 + row) * DIM + k0 + q * 4);
                As[q * 4 + 0][row] = v.x; As[q * 4 + 1][row] = v.y;
                As[q * 4 + 2][row] = v.z; As[q * 4 + 3][row] = v.w;
            }
            // B tile: 128 codes x 16 k
#pragma unroll
            for (int r2 = 0; r2 < 2; r2++) {
                int f = t + r2 * 256;
                int row = f >> 2;
                int q   = f & 3;
                float4 v = *reinterpret_cast<const float4*>(
                    CB + (size_t)(col0 + row) * DIM + k0 + q * 4);
                Bs[q * 4 + 0][row] = v.x; Bs[q * 4 + 1][row] = v.y;
                Bs[q * 4 + 2][row] = v.z; Bs[q * 4 + 3][row] = v.w;
            }
            __syncthreads();
#pragma unroll
            for (int k = 0; k < KC; k++) {
                float a[8], b[8];
                *reinterpret_cast<float4*>(&a[0]) = *reinterpret_cast<const float4*>(&As[k][ty * 8]);
                *reinterpret_cast<float4*>(&a[4]) = *reinterpret_cast<const float4*>(&As[k][ty * 8 + 4]);
                *reinterpret_cast<float4*>(&b[0]) = *reinterpret_cast<const float4*>(&Bs[k][tx * 8]);
                *reinterpret_cast<float4*>(&b[4]) = *reinterpret_cast<const float4*>(&Bs[k][tx * 8 + 4]);
#pragma unroll
                for (int i = 0; i < 8; i++)
#pragma unroll
                    for (int j = 0; j < 8; j++)
                        acc[i][j] = fmaf(a[i], b[j], acc[i][j]);
            }
        }
        // Epilogue: exact reference rounding sequence + running argmin
#pragma unroll
        for (int i = 0; i < 8; i++) {
#pragma unroll
            for (int j = 0; j < 8; j++) {
                float t2 = __fmul_rn(2.0f, acc[i][j]);
                float d  = __fadd_rn(__fadd_rn(x2r[i], -t2), c2s[tx * 8 + j]);
                if (d < bestv[i]) { bestv[i] = d; besti[i] = col0 + tx * 8 + j; }
            }
        }
    }

    // Cross-thread (16 tx lanes per row) reduction with index tie-break
    __syncthreads();
#pragma unroll
    for (int i = 0; i < 8; i++) {
        redv[ty * 8 + i][tx] = bestv[i];
        redi[ty * 8 + i][tx] = besti[i];
    }
    __syncthreads();
    if (t < TM) {
        float bv = redv[t][0];
        int   bi = redi[t][0];
#pragma unroll
        for (int c = 1; c < 16; c++) {
            float v = redv[t][c]; int ix = redi[t][c];
            if (v < bv || (v == bv && ix < bi)) { bv = v; bi = ix; }
        }
        g_pval[chunk * NROWS + row0 + t] = bv;
        g_pidx[chunk * NROWS + row0 + t] = bi;
    }
}

// ---------------------------------------------------------------------------
// Merge NSPLIT partials per row (ascending chunk => index order preserved)
__global__ void merge_kernel(float* __restrict__ out, int out_size) {
    int r = blockIdx.x * blockDim.x + threadIdx.x;
    if (r >= NROWS) return;
    float bv = g_pval[r];
    int   bi = g_pidx[r];
#pragma unroll
    for (int c = 1; c < NSPLIT; c++) {
        float v = g_pval[c * NROWS + r];
        int  ix = g_pidx[c * NROWS + r];
        if (v < bv || (v == bv && ix < bi)) { bv = v; bi = ix; }
    }
    g_idx[r] = bi;
    if (out_size >= NROWS * DIM + 1 + NROWS)
        out[NROWS * DIM + 1 + r] = (float)bi;        // indices as f32
    else if (out_size == NROWS)
        out[r] = (float)bi;                          // indices-only fallback
}

// ---------------------------------------------------------------------------
// Gather quantized = codebook[idx] + accumulate sum((q - x)^2) in double
__global__ void gather_kernel(const float* __restrict__ X,
                              const float* __restrict__ CB,
                              float* __restrict__ out, int out_size) {
    int gwarp = (blockIdx.x * blockDim.x + threadIdx.x) >> 5;  // row
    int lane  = threadIdx.x & 31;
    int row   = gwarp;
    int idx   = g_idx[row];
    const float4* cp = reinterpret_cast<const float4*>(CB + (size_t)idx * DIM);
    const float4* xp = reinterpret_cast<const float4*>(X  + (size_t)row * DIM);
    float4* op = reinterpret_cast<float4*>(out + (size_t)row * DIM);
    const bool write_q = (out_size >= NROWS * DIM);
    double s = 0.0;
#pragma unroll
    for (int q = 0; q < 4; q++) {
        float4 c = cp[lane + 32 * q];
        float4 x = xp[lane + 32 * q];
        if (write_q) op[lane + 32 * q] = c;
        float dx = c.x - x.x, dy = c.y - x.y, dz = c.z - x.z, dw = c.w - x.w;
        s += (double)dx * dx + (double)dy * dy + (double)dz * dz + (double)dw * dw;
    }
#pragma unroll
    for (int o = 16; o; o >>= 1) s += __shfl_xor_sync(0xFFFFFFFFu, s, o);
    __shared__ double ss[8];
    if (lane == 0) ss[threadIdx.x >> 5] = s;
    __syncthreads();
    if (threadIdx.x == 0) {
        double tot = 0.0;
#pragma unroll
        for (int w = 0; w < 8; w++) tot += ss[w];
        atomicAdd(&g_loss, tot);
    }
}

// loss = q_latent + 0.25*e_latent = 1.25 * mean((q - x)^2)  (values identical)
__global__ void loss_kernel(float* __restrict__ out, int out_size) {
    if (out_size >= NROWS * DIM + 1)
        out[NROWS * DIM] = (float)(1.25 * g_loss / ((double)NROWS * (double)DIM));
    else if (out_size == 1)
        out[0] = (float)(1.25 * g_loss / ((double)NROWS * (double)DIM));
}

// ---------------------------------------------------------------------------
extern "C" void kernel_launch(void* const* d_in, const int* in_sizes, int n_in,
                              void* d_out, int out_size) {
    const float* X  = (const float*)d_in[0];   // [8,1024,512] f32
    const float* CB = (const float*)d_in[1];   // [16384,512] f32
    float* out = (float*)d_out;

    c2_kernel<<<KCODES / 8, 256>>>(CB);
    x2_kernel<<<NROWS / 256, 256>>>(X);
    {
        dim3 grid(NROWS / TM, NSPLIT);
        argmin_kernel<<<grid, 256>>>(X, CB);
    }
    merge_kernel<<<NROWS / 256, 256>>>(out, out_size);
    gather_kernel<<<NROWS / 8, 256>>>(X, CB, out, out_size);
    loss_kernel<<<1, 1>>>(out, out_size);
}

// round 3
// speedup vs baseline: 1.5356x; 1.5356x over previous
#include <cuda_runtime.h>
#include <cstdint>

#define NROWS 8192
#define DIM   512
#define KCODES 16384
#define NSPLIT 8
#define TM 128
#define TN 128
#define KC 16
#define CHUNK (KCODES / NSPLIT)          // 2048
#define TILES_PER_CHUNK (CHUNK / TN)     // 16
#define NKCHUNK (DIM / KC)               // 32

// Device-global scratch (no runtime allocation allowed)
__device__ float  g_xt[DIM * NROWS];      // X^T  [512][8192]
__device__ float  g_cbt[DIM * KCODES];    // CB^T [512][16384]
__device__ float  g_c2[KCODES];
__device__ float  g_x2[NROWS];
__device__ float  g_pval[NSPLIT * NROWS];
__device__ int    g_pidx[NSPLIT * NROWS];
__device__ int    g_idx[NROWS];
__device__ double g_loss;

static __device__ __forceinline__ uint32_t sptr(const void* p) {
    return (uint32_t)__cvta_generic_to_shared(p);
}
#define CP_ASYNC16(dst, src) \
    asm volatile("cp.async.cg.shared.global [%0], [%1], 16;" :: "r"(dst), "l"(src))
#define CP_COMMIT() asm volatile("cp.async.commit_group;")
#define CP_WAIT(n)  asm volatile("cp.async.wait_group %0;" :: "n"(n))

// ---------------------------------------------------------------------------
// Tiled transpose: out[c][r] = in[r][c]
__global__ void transpose_kernel(const float* __restrict__ in, float* __restrict__ out,
                                 int rows, int cols) {
    __shared__ float tile[32][33];
    const int bx = blockIdx.x * 32;   // col base
    const int by = blockIdx.y * 32;   // row base
    const int tx = threadIdx.x, ty = threadIdx.y;  // 32 x 8
#pragma unroll
    for (int r = 0; r < 32; r += 8)
        tile[ty + r][tx] = in[(size_t)(by + ty + r) * cols + bx + tx];
    __syncthreads();
#pragma unroll
    for (int r = 0; r < 32; r += 8)
        out[(size_t)(bx + ty + r) * rows + by + tx] = tile[tx][ty + r];
}

// ---------------------------------------------------------------------------
__global__ void c2_kernel(const float* __restrict__ cb) {
    const int row  = blockIdx.x * 8 + (threadIdx.x >> 5);
    const int lane = threadIdx.x & 31;
    const float4* p = reinterpret_cast<const float4*>(cb + (size_t)row * DIM);
    float s = 0.f;
#pragma unroll
    for (int q = 0; q < 4; q++) {
        float4 v = p[lane + 32 * q];
        s += v.x * v.x + v.y * v.y + v.z * v.z + v.w * v.w;
    }
#pragma unroll
    for (int o = 16; o; o >>= 1) s += __shfl_xor_sync(0xFFFFFFFFu, s, o);
    if (lane == 0) g_c2[row] = s;
}

// x2 strict sequential fp32 (matches reference rounding); also zeroes loss
__global__ void x2_kernel(const float* __restrict__ x) {
    const int row = blockIdx.x * blockDim.x + threadIdx.x;
    if (row == 0) g_loss = 0.0;
    if (row >= NROWS) return;
    const float* p = x + (size_t)row * DIM;
    float acc = 0.f;
    for (int i = 0; i < DIM; i++) {
        float v = __ldg(p + i);
        acc = __fadd_rn(acc, __fmul_rn(v, v));
    }
    g_x2[row] = acc;
}

// ---------------------------------------------------------------------------
// Fused distance + argmin. Distances bitwise-identical to the round-1 kernel:
// same k-sequential FMA chains (f32x2 lanes are IEEE fma.rn), same epilogue
// rounding d = fl(fl(x2 - fl(2*dot)) + c2), same first-index tie-break.
__global__ __launch_bounds__(256, 2)
void argmin_kernel(const float* __restrict__ XT, const float* __restrict__ CBT) {
    __shared__ float As[2][KC][TM];   // 16 KB
    __shared__ float Bs[2][KC][TN];   // 16 KB
    __shared__ float c2s[CHUNK];      //  8 KB

    const int t  = threadIdx.x;
    const int tx = t & 15;
    const int ty = t >> 4;
    const int row0     = blockIdx.x * TM;
    const int chunk    = blockIdx.y;
    const int col_base = chunk * CHUNK;

    for (int i = t; i < CHUNK; i += 256) c2s[i] = g_c2[col_base + i];

    float x2r[8];
#pragma unroll
    for (int i = 0; i < 8; i++) x2r[i] = g_x2[row0 + ty * 8 + i];

    float bestv[8]; int besti[8];
#pragma unroll
    for (int i = 0; i < 8; i++) { bestv[i] = 3.4e38f; besti[i] = 0x7fffffff; }

    // Per-thread cp.async unit assignment: 2 units for A, 2 for B per k-chunk.
    const int k_u0 = t >> 5;            // 0..7
    const int k_u1 = (t + 256) >> 5;    // 8..15
    const int rg   = (t & 31) * 4;      // float offset within row-of-128

    for (int nt = 0; nt < TILES_PER_CHUNK; nt++) {
        const int col0 = col_base + nt * TN;

        unsigned long long acc2[8][4];
#pragma unroll
        for (int i = 0; i < 8; i++)
#pragma unroll
            for (int jp = 0; jp < 4; jp++) acc2[i][jp] = 0ull;

        auto issue = [&](int kc, int bufsel) {
            const size_t kbase = (size_t)(kc * KC);
            CP_ASYNC16(sptr(&As[bufsel][k_u0][rg]),
                       XT + (kbase + k_u0) * (size_t)NROWS + row0 + rg);
            CP_ASYNC16(sptr(&As[bufsel][k_u1][rg]),
                       XT + (kbase + k_u1) * (size_t)NROWS + row0 + rg);
            CP_ASYNC16(sptr(&Bs[bufsel][k_u0][rg]),
                       CBT + (kbase + k_u0) * (size_t)KCODES + col0 + rg);
            CP_ASYNC16(sptr(&Bs[bufsel][k_u1][rg]),
                       CBT + (kbase + k_u1) * (size_t)KCODES + col0 + rg);
            CP_COMMIT();
        };

        issue(0, 0);
        issue(1, 1);

        for (int c = 0; c < NKCHUNK; c++) {
            if (c < NKCHUNK - 1) { CP_WAIT(1); } else { CP_WAIT(0); }
            __syncthreads();
            const int buf = c & 1;
#pragma unroll
            for (int k = 0; k < KC; k++) {
                float4 a0 = *reinterpret_cast<const float4*>(&As[buf][k][ty * 8]);
                float4 a1 = *reinterpret_cast<const float4*>(&As[buf][k][ty * 8 + 4]);
                ulonglong2 b01 = *reinterpret_cast<const ulonglong2*>(&Bs[buf][k][tx * 8]);
                ulonglong2 b23 = *reinterpret_cast<const ulonglong2*>(&Bs[buf][k][tx * 8 + 4]);
                unsigned long long bb[4] = {b01.x, b01.y, b23.x, b23.y};
                float av[8] = {a0.x, a0.y, a0.z, a0.w, a1.x, a1.y, a1.z, a1.w};
#pragma unroll
                for (int i = 0; i < 8; i++) {
                    unsigned long long a2;
                    asm("mov.b64 %0, {%1, %1};" : "=l"(a2) : "r"(__float_as_uint(av[i])));
#pragma unroll
                    for (int jp = 0; jp < 4; jp++)
                        asm("fma.rn.f32x2 %0, %1, %2, %0;"
                            : "+l"(acc2[i][jp]) : "l"(a2), "l"(bb[jp]));
                }
            }
            __syncthreads();
            if (c + 2 < NKCHUNK) issue(c + 2, buf);
        }

        // Epilogue: exact reference rounding + running argmin (j ascending)
#pragma unroll
        for (int i = 0; i < 8; i++) {
#pragma unroll
            for (int jp = 0; jp < 4; jp++) {
                uint32_t lo, hi;
                asm("mov.b64 {%0, %1}, %2;" : "=r"(lo), "=r"(hi) : "l"(acc2[i][jp]));
                float vlo = __uint_as_float(lo);
                float vhi = __uint_as_float(hi);
                int cloc = nt * TN + tx * 8 + jp * 2;
                float d0 = __fadd_rn(__fadd_rn(x2r[i], -__fmul_rn(2.0f, vlo)), c2s[cloc]);
                float d1 = __fadd_rn(__fadd_rn(x2r[i], -__fmul_rn(2.0f, vhi)), c2s[cloc + 1]);
                if (d0 < bestv[i]) { bestv[i] = d0; besti[i] = col_base + cloc; }
                if (d1 < bestv[i]) { bestv[i] = d1; besti[i] = col_base + cloc + 1; }
            }
        }
    }

    // Cross-lane reduction over the 16 tx lanes (lexicographic (val, idx) min)
#pragma unroll
    for (int i = 0; i < 8; i++) {
        float bv = bestv[i]; int bi = besti[i];
#pragma unroll
        for (int o = 8; o; o >>= 1) {
            float ov = __shfl_xor_sync(0xFFFFFFFFu, bv, o);
            int   oi = __shfl_xor_sync(0xFFFFFFFFu, bi, o);
            if (ov < bv || (ov == bv && oi < bi)) { bv = ov; bi = oi; }
        }
        if (tx == 0) {
            g_pval[chunk * NROWS + row0 + ty * 8 + i] = bv;
            g_pidx[chunk * NROWS + row0 + ty * 8 + i] = bi;
        }
    }
}

// ---------------------------------------------------------------------------
__global__ void merge_kernel(float* __restrict__ out, int out_size) {
    const int r = blockIdx.x * blockDim.x + threadIdx.x;
    if (r >= NROWS) return;
    float bv = g_pval[r];
    int   bi = g_pidx[r];
#pragma unroll
    for (int c = 1; c < NSPLIT; c++) {
        float v = g_pval[c * NROWS + r];
        int  ix = g_pidx[c * NROWS + r];
        if (v < bv || (v == bv && ix < bi)) { bv = v; bi = ix; }
    }
    g_idx[r] = bi;
    if (out_size >= NROWS * DIM + 1 + NROWS)
        out[NROWS * DIM + 1 + r] = (float)bi;
    else if (out_size == NROWS)
        out[r] = (float)bi;
}

// ---------------------------------------------------------------------------
// Gather with STE rounding emulation: out = fl(x + fl(q - x))
__global__ void gather_kernel(const float* __restrict__ X,
                              const float* __restrict__ CB,
                              float* __restrict__ out, int out_size) {
    const int row  = (blockIdx.x * blockDim.x + threadIdx.x) >> 5;
    const int lane = threadIdx.x & 31;
    const int idx  = g_idx[row];
    const float4* cp = reinterpret_cast<const float4*>(CB + (size_t)idx * DIM);
    const float4* xp = reinterpret_cast<const float4*>(X  + (size_t)row * DIM);
    float4* op = reinterpret_cast<float4*>(out + (size_t)row * DIM);
    const bool write_q = (out_size >= NROWS * DIM);
    double s = 0.0;
#pragma unroll
    for (int q = 0; q < 4; q++) {
        float4 c = cp[lane + 32 * q];
        float4 x = xp[lane + 32 * q];
        if (write_q) {
            float4 o;
            o.x = __fadd_rn(x.x, __fsub_rn(c.x, x.x));
            o.y = __fadd_rn(x.y, __fsub_rn(c.y, x.y));
            o.z = __fadd_rn(x.z, __fsub_rn(c.z, x.z));
            o.w = __fadd_rn(x.w, __fsub_rn(c.w, x.w));
            op[lane + 32 * q] = o;
        }
        float dx = c.x - x.x, dy = c.y - x.y, dz = c.z - x.z, dw = c.w - x.w;
        s += (double)dx * dx + (double)dy * dy + (double)dz * dz + (double)dw * dw;
    }
#pragma unroll
    for (int o = 16; o; o >>= 1) s += __shfl_xor_sync(0xFFFFFFFFu, s, o);
    __shared__ double ss[8];
    if (lane == 0) ss[threadIdx.x >> 5] = s;
    __syncthreads();
    if (threadIdx.x == 0) {
        double tot = 0.0;
#pragma unroll
        for (int w = 0; w < 8; w++) tot += ss[w];
        atomicAdd(&g_loss, tot);
    }
}

__global__ void loss_kernel(float* __restrict__ out, int out_size) {
    if (out_size >= NROWS * DIM + 1)
        out[NROWS * DIM] = (float)(1.25 * g_loss / ((double)NROWS * (double)DIM));
    else if (out_size == 1)
        out[0] = (float)(1.25 * g_loss / ((double)NROWS * (double)DIM));
}

// ---------------------------------------------------------------------------
extern "C" void kernel_launch(void* const* d_in, const int* in_sizes, int n_in,
                              void* d_out, int out_size) {
    const float* X  = (const float*)d_in[0];
    const float* CB = (const float*)d_in[1];
    float* out = (float*)d_out;

    float* xt;  cudaGetSymbolAddress((void**)&xt,  g_xt);
    float* cbt; cudaGetSymbolAddress((void**)&cbt, g_cbt);

    {
        dim3 blk(32, 8);
        dim3 g1(DIM / 32, NROWS / 32);
        transpose_kernel<<<g1, blk>>>(X, xt, NROWS, DIM);
        dim3 g2(DIM / 32, KCODES / 32);
        transpose_kernel<<<g2, blk>>>(CB, cbt, KCODES, DIM);
    }
    c2_kernel<<<KCODES / 8, 256>>>(CB);
    x2_kernel<<<NROWS / 256, 256>>>(X);
    {
        dim3 grid(NROWS / TM, NSPLIT);
        argmin_kernel<<<grid, 256>>>(xt, cbt);
    }
    merge_kernel<<<NROWS / 256, 256>>>(out, out_size);
    gather_kernel<<<NROWS / 8, 256>>>(X, CB, out, out_size);
    loss_kernel<<<1, 1>>>(out, out_size);
}